// round 4
// baseline (speedup 1.0000x reference)
#include <cuda_runtime.h>
#include <cstdint>

#define N_TOK   65536
#define K_IN    64
#define E_DIM   512
#define V_SIZE  2048
#define NCHUNK  4
#define VCHUNK  (V_SIZE / NCHUNK)    // 512 codes per chunk

typedef unsigned long long ull;

// ---- scratch (device globals: no runtime allocation allowed) ----
__device__ float g_zp[(size_t)N_TOK * E_DIM];   // pre-conv output  [N, 512]
__device__ float g_C [N_TOK];                   // |zp|^2 per row
__device__ float g_e2[V_SIZE];                  // |emb|^2 per code
__device__ int   g_tok[N_TOK];                  // argmin tokens
__device__ float g_P [(size_t)V_SIZE * 64];     // emb @ post_W + post_b
__device__ float g_pv[NCHUNK][N_TOK];           // per-chunk best value
__device__ int   g_pi[NCHUNK][N_TOK];           // per-chunk best index

// ---- packed fp32x2 helpers (each lane is exact IEEE fp32 FMA) ----
__device__ __forceinline__ ull fma2(ull a, ull b, ull c) {
    ull d;
    asm("fma.rn.f32x2 %0, %1, %2, %3;" : "=l"(d) : "l"(a), "l"(b), "l"(c));
    return d;
}
__device__ __forceinline__ ull dup2(float x) {
    ull d;
    asm("mov.b64 %0, {%1, %1};" : "=l"(d) : "f"(x));
    return d;
}
__device__ __forceinline__ ull pack2(float x, float y) {
    ull d;
    asm("mov.b64 %0, {%1, %2};" : "=l"(d) : "f"(x), "f"(y));
    return d;
}
__device__ __forceinline__ float2 unpack2(ull v) {
    float2 r;
    asm("mov.b64 {%0, %1}, %2;" : "=f"(r.x), "=f"(r.y) : "l"(v));
    return r;
}

// ============================================================
// Kernel 0: e2[v] = sum_k emb[v,k]^2
// ============================================================
__global__ void e2_kernel(const float* __restrict__ emb) {
    int v = blockIdx.x;
    const float* row = emb + (size_t)v * E_DIM;
    float s = 0.f;
    for (int k = threadIdx.x; k < E_DIM; k += 128) {
        float x = row[k];
        s = fmaf(x, x, s);
    }
    for (int off = 16; off > 0; off >>= 1)
        s += __shfl_down_sync(0xffffffffu, s, off);
    __shared__ float ws[4];
    int lane = threadIdx.x & 31, warp = threadIdx.x >> 5;
    if (lane == 0) ws[warp] = s;
    __syncthreads();
    if (threadIdx.x == 0)
        g_e2[v] = ws[0] + ws[1] + ws[2] + ws[3];
}

// ============================================================
// Kernel 1: zp = z @ pre_W + pre_b, and C = |zp|^2
// ============================================================
__global__ __launch_bounds__(128) void pre_kernel(
    const float* __restrict__ z, const float* __restrict__ W,
    const float* __restrict__ b)
{
    int n = blockIdx.x;
    __shared__ float zs[K_IN];
    if (threadIdx.x < K_IN) zs[threadIdx.x] = z[(size_t)n * K_IN + threadIdx.x];
    __syncthreads();

    int j0 = threadIdx.x;
    float acc[4];
    #pragma unroll
    for (int i = 0; i < 4; i++) acc[i] = b[j0 + 128 * i];

    #pragma unroll 8
    for (int k = 0; k < K_IN; k++) {
        float zk = zs[k];
        const float* Wr = W + (size_t)k * E_DIM + j0;
        #pragma unroll
        for (int i = 0; i < 4; i++)
            acc[i] = fmaf(zk, Wr[128 * i], acc[i]);
    }

    float* zpr = g_zp + (size_t)n * E_DIM + j0;
    float s = 0.f;
    #pragma unroll
    for (int i = 0; i < 4; i++) {
        zpr[128 * i] = acc[i];
        s = fmaf(acc[i], acc[i], s);
    }
    for (int off = 16; off > 0; off >>= 1)
        s += __shfl_down_sync(0xffffffffu, s, off);
    __shared__ float ws[4];
    int lane = threadIdx.x & 31, warp = threadIdx.x >> 5;
    if (lane == 0) ws[warp] = s;
    __syncthreads();
    if (threadIdx.x == 0)
        g_C[n] = ws[0] + ws[1] + ws[2] + ws[3];
}

// ============================================================
// Kernel 2: fused distance GEMM + argmin, packed FFMA2,
// 512 threads, register-prefetch pipeline, codebook chunked.
// block: 128 rows x 512 codes (one chunk), tiles 128x256xK16.
// per thread: 4 rows x 16 codes. Sequential k chain per output
// -> bitwise identical distances.
// ============================================================
#define DBM 128
#define DBV 256
#define DBK 16
#define NKT (E_DIM / DBK)          // 32 k-tiles
#define NVT (VCHUNK / DBV)         // 2 v-tiles per chunk
#define NT  (NKT * NVT)            // 64 tiles per block

__global__ __launch_bounds__(512, 1) void dist_kernel(
    const float* __restrict__ emb)
{
    __shared__ float As[DBK][DBM + 4];
    __shared__ float Bs[DBK][DBV + 4];

    int m0    = blockIdx.x * DBM;
    int chunk = blockIdx.y;
    int vc    = chunk * VCHUNK;

    int tid = threadIdx.x;
    int tx  = tid & 15;    // code direction (16)
    int ty  = tid >> 4;    // row direction  (32)
    int row0 = ty * 4;

    // load/store geometry: 1 A float4 + 2 B float4 per thread per tile
    int mA  = tid >> 2;            // 0..127
    int kq4 = (tid & 3) * 4;
    const float* aBase = g_zp + (size_t)(m0 + mA) * E_DIM + kq4;
    const float* bBase = emb + (size_t)(vc + mA) * E_DIM + kq4;
    float* sA = &As[kq4][mA];
    float* sB0 = &Bs[kq4][mA];
    float* sB1 = &Bs[kq4][mA + 128];

    float Ci[4];
    #pragma unroll
    for (int i = 0; i < 4; i++) Ci[i] = g_C[m0 + row0 + i];

    float bestv[4];
    int   besti[4];
    #pragma unroll
    for (int i = 0; i < 4; i++) { bestv[i] = 3.4e38f; besti[i] = 0; }

    ull acc[4][8];

    // prefetch tile 0  (t=0: k0=0, v0=vc)
    float4 pA, pB0, pB1;
    pA  = *(const float4*)(aBase);
    pB0 = *(const float4*)(bBase);
    pB1 = *(const float4*)(bBase + (size_t)128 * E_DIM);

    for (int t = 0; t < NT; t++) {
        // ---- store prefetched tile to smem (transpose) ----
        sA [0*(DBM+4)] = pA.x;  sA [1*(DBM+4)] = pA.y;
        sA [2*(DBM+4)] = pA.z;  sA [3*(DBM+4)] = pA.w;
        sB0[0*(DBV+4)] = pB0.x; sB0[1*(DBV+4)] = pB0.y;
        sB0[2*(DBV+4)] = pB0.z; sB0[3*(DBV+4)] = pB0.w;
        sB1[0*(DBV+4)] = pB1.x; sB1[1*(DBV+4)] = pB1.y;
        sB1[2*(DBV+4)] = pB1.z; sB1[3*(DBV+4)] = pB1.w;

        // ---- issue prefetch for tile t+1 ----
        {
            int tn = (t + 1 < NT) ? t + 1 : t;
            int k1 = (tn & (NKT - 1)) * DBK;
            int voff = (tn >> 5) * DBV;   // 0 or 256
            pA  = *(const float4*)(aBase + k1);
            const float* bb = bBase + (size_t)voff * E_DIM + k1;
            pB0 = *(const float4*)(bb);
            pB1 = *(const float4*)(bb + (size_t)128 * E_DIM);
        }

        if ((t & (NKT - 1)) == 0) {
            #pragma unroll
            for (int i = 0; i < 4; i++)
                #pragma unroll
                for (int j = 0; j < 8; j++) acc[i][j] = 0ull;
        }

        __syncthreads();

        // ---- compute 16 kk steps ----
        #pragma unroll
        for (int kk = 0; kk < DBK; kk++) {
            float4 a = *(const float4*)&As[kk][row0];
            ull ad[4];
            ad[0] = dup2(a.x); ad[1] = dup2(a.y);
            ad[2] = dup2(a.z); ad[3] = dup2(a.w);
            #pragma unroll
            for (int g = 0; g < 4; g++) {
                float4 b = *(const float4*)&Bs[kk][(g * 16 + tx) * 4];
                ull b0 = pack2(b.x, b.y);
                ull b1 = pack2(b.z, b.w);
                #pragma unroll
                for (int i = 0; i < 4; i++) {
                    acc[i][g * 2 + 0] = fma2(ad[i], b0, acc[i][g * 2 + 0]);
                    acc[i][g * 2 + 1] = fma2(ad[i], b1, acc[i][g * 2 + 1]);
                }
            }
        }

        __syncthreads();

        // ---- end of a v-tile's k sweep: fold argmin ----
        if ((t & (NKT - 1)) == NKT - 1) {
            int v0 = vc + (t >> 5) * DBV;
            #pragma unroll
            for (int g = 0; g < 4; g++) {
                int vb = v0 + (g * 16 + tx) * 4;
                float e0 = g_e2[vb + 0];
                float e1 = g_e2[vb + 1];
                float e2v = g_e2[vb + 2];
                float e3 = g_e2[vb + 3];
                #pragma unroll
                for (int i = 0; i < 4; i++) {
                    float2 p0 = unpack2(acc[i][g * 2 + 0]);
                    float2 p1 = unpack2(acc[i][g * 2 + 1]);
                    float d;
                    d = fmaf(-2.0f, p0.x, Ci[i] + e0);
                    if (d < bestv[i]) { bestv[i] = d; besti[i] = vb + 0; }
                    d = fmaf(-2.0f, p0.y, Ci[i] + e1);
                    if (d < bestv[i]) { bestv[i] = d; besti[i] = vb + 1; }
                    d = fmaf(-2.0f, p1.x, Ci[i] + e2v);
                    if (d < bestv[i]) { bestv[i] = d; besti[i] = vb + 2; }
                    d = fmaf(-2.0f, p1.y, Ci[i] + e3);
                    if (d < bestv[i]) { bestv[i] = d; besti[i] = vb + 3; }
                }
            }
        }
    }

    // cross-tx reduction: 16 tx threads of one ty occupy one half-warp
    #pragma unroll
    for (int i = 0; i < 4; i++) {
        float v = bestv[i];
        int   idx = besti[i];
        #pragma unroll
        for (int off = 8; off > 0; off >>= 1) {
            float ov = __shfl_xor_sync(0xffffffffu, v, off);
            int   oi = __shfl_xor_sync(0xffffffffu, idx, off);
            if (ov < v || (ov == v && oi < idx)) { v = ov; idx = oi; }
        }
        if (tx == 0) {
            int n = m0 + row0 + i;
            g_pv[chunk][n] = v;
            g_pi[chunk][n] = idx;
        }
    }
}

// ============================================================
// Kernel 3: merge per-chunk argmins (ascending chunk = ascending
// index range, strict < keeps first-min semantics)
// ============================================================
__global__ __launch_bounds__(256) void merge_kernel(float* __restrict__ out_tok)
{
    int n = blockIdx.x * 256 + threadIdx.x;
    float bv = g_pv[0][n];
    int   bi = g_pi[0][n];
    #pragma unroll
    for (int c = 1; c < NCHUNK; c++) {
        float v = g_pv[c][n];
        int   i = g_pi[c][n];
        if (v < bv) { bv = v; bi = i; }
    }
    g_tok[n] = bi;
    out_tok[n] = (float)bi;
}

// ============================================================
// Kernel 4: P = emb @ post_W + post_b   [2048, 64]
// ============================================================
#define BM 64
#define BK 32

__global__ __launch_bounds__(256) void pmat_kernel(
    const float* __restrict__ emb, const float* __restrict__ W,
    const float* __restrict__ b)
{
    __shared__ float As2[BK][BM + 4];
    __shared__ float Bs2[BK][64 + 4];

    int m0  = blockIdx.x * BM;
    int tid = threadIdx.x;
    int tx  = tid & 15;
    int ty  = tid >> 4;

    float acc[4][4];
    #pragma unroll
    for (int i = 0; i < 4; i++)
        #pragma unroll
        for (int j = 0; j < 4; j++) acc[i][j] = 0.f;

    for (int k0 = 0; k0 < E_DIM; k0 += BK) {
        #pragma unroll
        for (int i = 0; i < 8; i++) {
            int idx = tid + 256 * i;
            int m = idx >> 5, kk = idx & 31;
            As2[kk][m] = emb[(size_t)(m0 + m) * E_DIM + k0 + kk];
        }
        #pragma unroll
        for (int i = 0; i < 8; i++) {
            int idx = tid + 256 * i;
            int kk = idx >> 6, j = idx & 63;
            Bs2[kk][j] = W[(size_t)(k0 + kk) * 64 + j];
        }
        __syncthreads();
        #pragma unroll
        for (int kk = 0; kk < BK; kk++) {
            float a[4], bb[4];
            *(float4*)a  = *(const float4*)&As2[kk][ty * 4];
            *(float4*)bb = *(const float4*)&Bs2[kk][tx * 4];
            #pragma unroll
            for (int i = 0; i < 4; i++)
                #pragma unroll
                for (int j = 0; j < 4; j++)
                    acc[i][j] = fmaf(a[i], bb[j], acc[i][j]);
        }
        __syncthreads();
    }

    float bb0 = b[tx * 4 + 0], bb1 = b[tx * 4 + 1],
          bb2 = b[tx * 4 + 2], bb3 = b[tx * 4 + 3];
    #pragma unroll
    for (int i = 0; i < 4; i++) {
        int n = m0 + ty * 4 + i;
        float4 r;
        r.x = acc[i][0] + bb0;
        r.y = acc[i][1] + bb1;
        r.z = acc[i][2] + bb2;
        r.w = acc[i][3] + bb3;
        *(float4*)&g_P[(size_t)n * 64 + tx * 4] = r;
    }
}

// ============================================================
// Kernel 5: z_q[n] = P[tok[n]]  (pure gather)
// ============================================================
__global__ __launch_bounds__(256) void gather_kernel(float* __restrict__ out)
{
    int idx = blockIdx.x * 256 + threadIdx.x;
    int n = idx >> 4;
    int c = idx & 15;
    int tok = g_tok[n];
    float4 v = *(const float4*)&g_P[(size_t)tok * 64 + c * 4];
    *(float4*)&out[(size_t)n * 64 + c * 4] = v;
}

// ============================================================
extern "C" void kernel_launch(void* const* d_in, const int* in_sizes, int n_in,
                              void* d_out, int out_size)
{
    const float* z      = (const float*)d_in[0];   // [N, 64]
    const float* emb_W  = (const float*)d_in[1];   // [2048, 512]
    const float* pre_W  = (const float*)d_in[2];   // [64, 512]
    const float* pre_b  = (const float*)d_in[3];   // [512]
    const float* post_W = (const float*)d_in[4];   // [512, 64]
    const float* post_b = (const float*)d_in[5];   // [64]

    float* out = (float*)d_out;
    float* out_tok = out;                 // [N] tokens (as float)
    float* out_zq  = out + N_TOK;         // [N, 64]

    e2_kernel   <<<V_SIZE, 128>>>(emb_W);
    pre_kernel  <<<N_TOK, 128>>>(z, pre_W, pre_b);
    pmat_kernel <<<V_SIZE / BM, 256>>>(emb_W, post_W, post_b);

    dim3 dgrid(N_TOK / DBM, NCHUNK);
    dist_kernel <<<dgrid, 512>>>(emb_W);

    merge_kernel<<<N_TOK / 256, 256>>>(out_tok);
    gather_kernel<<<(N_TOK * 16) / 256, 256>>>(out_zq);
}

// round 5
// speedup vs baseline: 1.2248x; 1.2248x over previous
#include <cuda_runtime.h>
#include <cstdint>

#define N_TOK   65536
#define K_IN    64
#define E_DIM   512
#define V_SIZE  2048
#define NCHUNK  2
#define VCHUNK  (V_SIZE / NCHUNK)    // 1024 codes per chunk

typedef unsigned long long ull;

// ---- scratch (device globals: no runtime allocation allowed) ----
__device__ float g_zp[(size_t)N_TOK * E_DIM];   // pre-conv output  [N, 512]
__device__ float g_C [N_TOK];                   // |zp|^2 per row
__device__ float g_e2[V_SIZE];                  // |emb|^2 per code
__device__ int   g_tok[N_TOK];                  // argmin tokens
__device__ float g_P [(size_t)V_SIZE * 64];     // emb @ post_W + post_b
__device__ float g_pv[NCHUNK][N_TOK];           // per-chunk best value
__device__ int   g_pi[NCHUNK][N_TOK];           // per-chunk best index

// ---- packed fp32x2 helpers (each lane is exact IEEE fp32 FMA) ----
__device__ __forceinline__ ull fma2(ull a, ull b, ull c) {
    ull d;
    asm("fma.rn.f32x2 %0, %1, %2, %3;" : "=l"(d) : "l"(a), "l"(b), "l"(c));
    return d;
}
__device__ __forceinline__ ull dup2(float x) {
    ull d;
    asm("mov.b64 %0, {%1, %1};" : "=l"(d) : "f"(x));
    return d;
}
__device__ __forceinline__ ull pack2(float x, float y) {
    ull d;
    asm("mov.b64 %0, {%1, %2};" : "=l"(d) : "f"(x), "f"(y));
    return d;
}
__device__ __forceinline__ float2 unpack2(ull v) {
    float2 r;
    asm("mov.b64 {%0, %1}, %2;" : "=f"(r.x), "=f"(r.y) : "l"(v));
    return r;
}

// ============================================================
// Kernel 0: e2[v] = sum_k emb[v,k]^2   (unchanged: passes exact)
// ============================================================
__global__ void e2_kernel(const float* __restrict__ emb) {
    int v = blockIdx.x;
    const float* row = emb + (size_t)v * E_DIM;
    float s = 0.f;
    for (int k = threadIdx.x; k < E_DIM; k += 128) {
        float x = row[k];
        s = fmaf(x, x, s);
    }
    for (int off = 16; off > 0; off >>= 1)
        s += __shfl_down_sync(0xffffffffu, s, off);
    __shared__ float ws[4];
    int lane = threadIdx.x & 31, warp = threadIdx.x >> 5;
    if (lane == 0) ws[warp] = s;
    __syncthreads();
    if (threadIdx.x == 0)
        g_e2[v] = ws[0] + ws[1] + ws[2] + ws[3];
}

// ============================================================
// Kernel 1: zp = z @ pre_W + pre_b (FFMA2), and C = |zp|^2
// per-column chain identical to reference path: bias init,
// k ascending fmaf. C order is irrelevant (row constant).
// ============================================================
__global__ __launch_bounds__(128) void pre_kernel(
    const float* __restrict__ z, const float* __restrict__ W,
    const float* __restrict__ b)
{
    int n = blockIdx.x;
    __shared__ float zs[K_IN];
    if (threadIdx.x < K_IN) zs[threadIdx.x] = z[(size_t)n * K_IN + threadIdx.x];
    __syncthreads();

    int j0 = threadIdx.x * 4;
    float4 b4 = *(const float4*)&b[j0];
    ull acc0 = pack2(b4.x, b4.y);
    ull acc1 = pack2(b4.z, b4.w);

    #pragma unroll 16
    for (int k = 0; k < K_IN; k++) {
        ull zk = dup2(zs[k]);
        float4 w = *(const float4*)&W[(size_t)k * E_DIM + j0];
        acc0 = fma2(zk, pack2(w.x, w.y), acc0);
        acc1 = fma2(zk, pack2(w.z, w.w), acc1);
    }

    float2 p0 = unpack2(acc0), p1 = unpack2(acc1);
    float4 r; r.x = p0.x; r.y = p0.y; r.z = p1.x; r.w = p1.y;
    *(float4*)&g_zp[(size_t)n * E_DIM + j0] = r;

    float s = p0.x * p0.x;
    s = fmaf(p0.y, p0.y, s);
    s = fmaf(p1.x, p1.x, s);
    s = fmaf(p1.y, p1.y, s);
    for (int off = 16; off > 0; off >>= 1)
        s += __shfl_down_sync(0xffffffffu, s, off);
    __shared__ float ws[4];
    int lane = threadIdx.x & 31, warp = threadIdx.x >> 5;
    if (lane == 0) ws[warp] = s;
    __syncthreads();
    if (threadIdx.x == 0)
        g_C[n] = ws[0] + ws[1] + ws[2] + ws[3];
}

// ============================================================
// Kernel 2: fused distance GEMM + argmin.
// R2 geometry (256 thr, 8 rows x 16 codes per thread, crossbar-
// optimal), double-buffered smem (48KB exactly, XOR swizzle for
// conflict-free STS), ONE bar per tile, codebook chunked by 2.
// Per-output FMA chain = sequential k 0..511 -> bitwise tokens.
// ============================================================
#define DBM 128
#define DBV 256
#define DBK 16
#define NKT (E_DIM / DBK)          // 32 k-tiles
#define NVT (VCHUNK / DBV)         // 4 v-tiles per chunk
#define NT  (NKT * NVT)            // 128 tiles per block

__global__ __launch_bounds__(256, 1) void dist_kernel(
    const float* __restrict__ emb)
{
    __shared__ float As[2][DBK][DBM];   // 16 KB
    __shared__ float Bs[2][DBK][DBV];   // 32 KB

    int m0 = blockIdx.x * DBM;
    int chunk = blockIdx.y;
    int vc = chunk * VCHUNK;

    int tid = threadIdx.x;
    int tx  = tid & 15;    // code direction
    int ty  = tid >> 4;    // row direction
    int row0 = ty * 8;

    int mA  = tid >> 2;            // 0..63
    int kq4 = (tid & 3) * 4;       // k offset of this thread's float4
    int sw  = kq4 << 1;            // store-column XOR swizzle ((r&12)<<1)
    int mAx = mA ^ sw;

    const float* aBase = g_zp + (size_t)(m0 + mA) * E_DIM + kq4;
    const float* bBase = emb  + (size_t)(vc + mA) * E_DIM + kq4;

    float Ci[8];
    #pragma unroll
    for (int i = 0; i < 8; i++) Ci[i] = g_C[m0 + row0 + i];

    float bestv[8];
    int   besti[8];
    #pragma unroll
    for (int i = 0; i < 8; i++) { bestv[i] = 3.4e38f; besti[i] = 0; }

    ull acc[8][8];
    float4 pA0, pA1, pB0, pB1, pB2, pB3;

    // tile load: tile index tt -> k offset + v offset
    #define LOAD_TILE(tt) do {                                              \
        int _k = ((tt) & (NKT - 1)) * DBK;                                  \
        int _v = ((tt) >> 5) * DBV;                                         \
        pA0 = *(const float4*)(aBase + _k);                                 \
        pA1 = *(const float4*)(aBase + (size_t)64 * E_DIM + _k);            \
        const float* _bb = bBase + (size_t)_v * E_DIM + _k;                 \
        pB0 = *(const float4*)(_bb);                                        \
        pB1 = *(const float4*)(_bb + (size_t)64  * E_DIM);                  \
        pB2 = *(const float4*)(_bb + (size_t)128 * E_DIM);                  \
        pB3 = *(const float4*)(_bb + (size_t)192 * E_DIM);                  \
    } while (0)

    #define STS_TILE(bf) do {                                               \
        float* _a = &As[bf][kq4][0];                                        \
        _a[0*DBM + mAx]      = pA0.x; _a[1*DBM + mAx]      = pA0.y;         \
        _a[2*DBM + mAx]      = pA0.z; _a[3*DBM + mAx]      = pA0.w;         \
        _a[0*DBM + mAx + 64] = pA1.x; _a[1*DBM + mAx + 64] = pA1.y;         \
        _a[2*DBM + mAx + 64] = pA1.z; _a[3*DBM + mAx + 64] = pA1.w;         \
        float* _b = &Bs[bf][kq4][0];                                        \
        _b[0*DBV + mAx]       = pB0.x; _b[1*DBV + mAx]       = pB0.y;       \
        _b[2*DBV + mAx]       = pB0.z; _b[3*DBV + mAx]       = pB0.w;       \
        _b[0*DBV + mAx + 64]  = pB1.x; _b[1*DBV + mAx + 64]  = pB1.y;       \
        _b[2*DBV + mAx + 64]  = pB1.z; _b[3*DBV + mAx + 64]  = pB1.w;       \
        _b[0*DBV + mAx + 128] = pB2.x; _b[1*DBV + mAx + 128] = pB2.y;       \
        _b[2*DBV + mAx + 128] = pB2.z; _b[3*DBV + mAx + 128] = pB2.w;       \
        _b[0*DBV + mAx + 192] = pB3.x; _b[1*DBV + mAx + 192] = pB3.y;       \
        _b[2*DBV + mAx + 192] = pB3.z; _b[3*DBV + mAx + 192] = pB3.w;       \
    } while (0)

    LOAD_TILE(0);
    STS_TILE(0);
    LOAD_TILE(1);
    __syncthreads();

    for (int t = 0; t < NT; t++) {
        int buf = t & 1;

        if (t + 1 < NT) {
            STS_TILE(buf ^ 1);                       // regs hold tile t+1
            int tt = (t + 2 < NT) ? t + 2 : NT - 1;
            LOAD_TILE(tt);                           // prefetch t+2
        }

        if ((t & (NKT - 1)) == 0) {
            #pragma unroll
            for (int i = 0; i < 8; i++)
                #pragma unroll
                for (int j = 0; j < 8; j++) acc[i][j] = 0ull;
        }

        // ---- compute 16 kk steps from buf ----
        #pragma unroll
        for (int kk = 0; kk < DBK; kk++) {
            const int s = (kk & 12) << 1;            // load-side swizzle
            float4 a01 = *(const float4*)&As[buf][kk][(row0 ^ s)];
            float4 a23 = *(const float4*)&As[buf][kk][(row0 ^ s) + 4];
            ull ad[8];
            ad[0] = dup2(a01.x); ad[1] = dup2(a01.y);
            ad[2] = dup2(a01.z); ad[3] = dup2(a01.w);
            ad[4] = dup2(a23.x); ad[5] = dup2(a23.y);
            ad[6] = dup2(a23.z); ad[7] = dup2(a23.w);
            #pragma unroll
            for (int g = 0; g < 4; g++) {
                float4 b = *(const float4*)&Bs[buf][kk][(((g * 16 + tx) * 4) ^ s)];
                ull b0 = pack2(b.x, b.y);
                ull b1 = pack2(b.z, b.w);
                #pragma unroll
                for (int i = 0; i < 8; i++) {
                    acc[i][g * 2 + 0] = fma2(ad[i], b0, acc[i][g * 2 + 0]);
                    acc[i][g * 2 + 1] = fma2(ad[i], b1, acc[i][g * 2 + 1]);
                }
            }
        }

        __syncthreads();   // single barrier per tile (double-buffered)

        // ---- end of a v-tile's k sweep: fold argmin (regs only) ----
        if ((t & (NKT - 1)) == NKT - 1) {
            int v0 = vc + (t >> 5) * DBV;
            #pragma unroll
            for (int g = 0; g < 4; g++) {
                int vb = v0 + (g * 16 + tx) * 4;
                float e0 = g_e2[vb + 0];
                float e1 = g_e2[vb + 1];
                float e2v = g_e2[vb + 2];
                float e3 = g_e2[vb + 3];
                #pragma unroll
                for (int i = 0; i < 8; i++) {
                    float2 p0 = unpack2(acc[i][g * 2 + 0]);
                    float2 p1 = unpack2(acc[i][g * 2 + 1]);
                    float d;
                    d = fmaf(-2.0f, p0.x, Ci[i] + e0);
                    if (d < bestv[i]) { bestv[i] = d; besti[i] = vb + 0; }
                    d = fmaf(-2.0f, p0.y, Ci[i] + e1);
                    if (d < bestv[i]) { bestv[i] = d; besti[i] = vb + 1; }
                    d = fmaf(-2.0f, p1.x, Ci[i] + e2v);
                    if (d < bestv[i]) { bestv[i] = d; besti[i] = vb + 2; }
                    d = fmaf(-2.0f, p1.y, Ci[i] + e3);
                    if (d < bestv[i]) { bestv[i] = d; besti[i] = vb + 3; }
                }
            }
        }
    }

    // cross-tx reduction: 16 tx threads of one ty share a half-warp
    #pragma unroll
    for (int i = 0; i < 8; i++) {
        float v = bestv[i];
        int   idx = besti[i];
        #pragma unroll
        for (int off = 8; off > 0; off >>= 1) {
            float ov = __shfl_xor_sync(0xffffffffu, v, off);
            int   oi = __shfl_xor_sync(0xffffffffu, idx, off);
            if (ov < v || (ov == v && oi < idx)) { v = ov; idx = oi; }
        }
        if (tx == 0) {
            int n = m0 + row0 + i;
            g_pv[chunk][n] = v;
            g_pi[chunk][n] = idx;
        }
    }
    #undef LOAD_TILE
    #undef STS_TILE
}

// ============================================================
// Kernel 3: merge per-chunk argmins (ascending chunk order,
// strict < keeps first-min semantics)
// ============================================================
__global__ __launch_bounds__(256) void merge_kernel(float* __restrict__ out_tok)
{
    int n = blockIdx.x * 256 + threadIdx.x;
    float bv = g_pv[0][n];
    int   bi = g_pi[0][n];
    #pragma unroll
    for (int c = 1; c < NCHUNK; c++) {
        float v = g_pv[c][n];
        int   i = g_pi[c][n];
        if (v < bv) { bv = v; bi = i; }
    }
    g_tok[n] = bi;
    out_tok[n] = (float)bi;
}

// ============================================================
// Kernel 4: P = emb @ post_W + post_b   [2048, 64]  (unchanged)
// ============================================================
#define BM 64
#define BK 32

__global__ __launch_bounds__(256) void pmat_kernel(
    const float* __restrict__ emb, const float* __restrict__ W,
    const float* __restrict__ b)
{
    __shared__ float As2[BK][BM + 4];
    __shared__ float Bs2[BK][64 + 4];

    int m0  = blockIdx.x * BM;
    int tid = threadIdx.x;
    int tx  = tid & 15;
    int ty  = tid >> 4;

    float acc[4][4];
    #pragma unroll
    for (int i = 0; i < 4; i++)
        #pragma unroll
        for (int j = 0; j < 4; j++) acc[i][j] = 0.f;

    for (int k0 = 0; k0 < E_DIM; k0 += BK) {
        #pragma unroll
        for (int i = 0; i < 8; i++) {
            int idx = tid + 256 * i;
            int m = idx >> 5, kk = idx & 31;
            As2[kk][m] = emb[(size_t)(m0 + m) * E_DIM + k0 + kk];
        }
        #pragma unroll
        for (int i = 0; i < 8; i++) {
            int idx = tid + 256 * i;
            int kk = idx >> 6, j = idx & 63;
            Bs2[kk][j] = W[(size_t)(k0 + kk) * 64 + j];
        }
        __syncthreads();
        #pragma unroll
        for (int kk = 0; kk < BK; kk++) {
            float a[4], bb[4];
            *(float4*)a  = *(const float4*)&As2[kk][ty * 4];
            *(float4*)bb = *(const float4*)&Bs2[kk][tx * 4];
            #pragma unroll
            for (int i = 0; i < 4; i++)
                #pragma unroll
                for (int j = 0; j < 4; j++)
                    acc[i][j] = fmaf(a[i], bb[j], acc[i][j]);
        }
        __syncthreads();
    }

    float bb0 = b[tx * 4 + 0], bb1 = b[tx * 4 + 1],
          bb2 = b[tx * 4 + 2], bb3 = b[tx * 4 + 3];
    #pragma unroll
    for (int i = 0; i < 4; i++) {
        int n = m0 + ty * 4 + i;
        float4 r;
        r.x = acc[i][0] + bb0;
        r.y = acc[i][1] + bb1;
        r.z = acc[i][2] + bb2;
        r.w = acc[i][3] + bb3;
        *(float4*)&g_P[(size_t)n * 64 + tx * 4] = r;
    }
}

// ============================================================
// Kernel 5: z_q[n] = P[tok[n]]  (pure gather)
// ============================================================
__global__ __launch_bounds__(256) void gather_kernel(float* __restrict__ out)
{
    int idx = blockIdx.x * 256 + threadIdx.x;
    int n = idx >> 4;
    int c = idx & 15;
    int tok = g_tok[n];
    float4 v = *(const float4*)&g_P[(size_t)tok * 64 + c * 4];
    *(float4*)&out[(size_t)n * 64 + c * 4] = v;
}

// ============================================================
extern "C" void kernel_launch(void* const* d_in, const int* in_sizes, int n_in,
                              void* d_out, int out_size)
{
    const float* z      = (const float*)d_in[0];   // [N, 64]
    const float* emb_W  = (const float*)d_in[1];   // [2048, 512]
    const float* pre_W  = (const float*)d_in[2];   // [64, 512]
    const float* pre_b  = (const float*)d_in[3];   // [512]
    const float* post_W = (const float*)d_in[4];   // [512, 64]
    const float* post_b = (const float*)d_in[5];   // [64]

    float* out = (float*)d_out;
    float* out_tok = out;                 // [N] tokens (as float)
    float* out_zq  = out + N_TOK;         // [N, 64]

    e2_kernel   <<<V_SIZE, 128>>>(emb_W);
    pre_kernel  <<<N_TOK, 128>>>(z, pre_W, pre_b);
    pmat_kernel <<<V_SIZE / BM, 256>>>(emb_W, post_W, post_b);

    dim3 dgrid(N_TOK / DBM, NCHUNK);
    dist_kernel <<<dgrid, 256>>>(emb_W);

    merge_kernel<<<N_TOK / 256, 256>>>(out_tok);
    gather_kernel<<<(N_TOK * 16) / 256, 256>>>(out_zq);
}